// round 1
// baseline (speedup 1.0000x reference)
#include <cuda_runtime.h>
#include <math.h>

// Problem constants
#define NBATCH 4096
#define NTOK   64      // agents per batch
#define DOBS   128
#define DMSG   64
#define NHEAD  4
#define HDIM   16
#define DINT   256

// Padded shared-memory leading dims (bank-conflict avoidance)
#define LD_QKV 196     // 192 + 4
#define LD_CTX 68      // 64 + 4
#define LD_Z   264     // 256 + 8

// Shared-memory layout (float offsets). Buffers alias across dead stages.
#define OFF_OBS 0          // 64x128           (live until int1)
#define OFF_H   8192       // 64x128           (enc1 out, dead after enc2)
#define OFF_MSG 16384      // 64x64            (dead after qkv)
#define OFF_QKV 20480      // 64x196           (dead after attention)
#define OFF_CTX 8192       // 64x68  (alias H)
#define OFF_AGG 12544      // 64x64
#define OFF_Z   16640      // 64x264 (alias MSG/QKV)
#define SMEM_FLOATS 33536
#define SMEM_BYTES  (SMEM_FLOATS * 4)

// Register-tiled smem GEMM: Y[64xOUT] = relu?(X[64xK] @ W[KxOUT] + bias)
// Thread tile: TJ output columns x TT tokens. 256 threads total.
template<int K, int LDX, int OUT, int LDY, int TJ, int TT, bool RELU>
__device__ __forceinline__ void gemm_s(int tid, const float* sX,
                                       const float* __restrict__ W,
                                       const float* __restrict__ bias,
                                       float* sY)
{
    constexpr int JG = OUT / TJ;
    constexpr int TG = NTOK / TT;
    static_assert(JG * TG == 256, "bad tiling");
    const int jg = tid % JG;
    const int tg = tid / JG;
    const int j0 = jg * TJ;
    const int t0 = tg * TT;
    float acc[TT][TJ];
#pragma unroll
    for (int jj = 0; jj < TJ; jj++) {
        float bv = bias[j0 + jj];
#pragma unroll
        for (int t = 0; t < TT; t++) acc[t][jj] = bv;
    }
#pragma unroll 4
    for (int k = 0; k < K; k++) {
        float w[TJ];
#pragma unroll
        for (int jj = 0; jj < TJ; jj++) w[jj] = W[k * OUT + j0 + jj];
        float x[TT];
#pragma unroll
        for (int t = 0; t < TT; t++) x[t] = sX[(t0 + t) * LDX + k];
#pragma unroll
        for (int t = 0; t < TT; t++)
#pragma unroll
            for (int jj = 0; jj < TJ; jj++)
                acc[t][jj] = fmaf(x[t], w[jj], acc[t][jj]);
    }
#pragma unroll
    for (int t = 0; t < TT; t++)
#pragma unroll
        for (int jj = 0; jj < TJ; jj++) {
            float v = acc[t][jj];
            if (RELU) v = fmaxf(v, 0.f);
            sY[(t0 + t) * LDY + j0 + jj] = v;
        }
}

extern __shared__ float smem[];

__global__ void __launch_bounds__(256, 1)
macs_kernel(const float* __restrict__ obs,
            const float* __restrict__ enc_w1, const float* __restrict__ enc_b1,
            const float* __restrict__ enc_w2, const float* __restrict__ enc_b2,
            const float* __restrict__ inp_w,  const float* __restrict__ inp_b,
            const float* __restrict__ out_w,  const float* __restrict__ out_b,
            const float* __restrict__ int_w1, const float* __restrict__ int_b1,
            const float* __restrict__ ln_g,   const float* __restrict__ ln_b,
            const float* __restrict__ int_w2, const float* __restrict__ int_b2,
            float* __restrict__ outE, float* __restrict__ outM)
{
    const int b   = blockIdx.x;
    const int tid = threadIdx.x;

    // ---- load obs tile (64x128 f32, coalesced float4) ----
    {
        const float4* g4 = (const float4*)(obs + (size_t)b * NTOK * DOBS);
        float4* s4 = (float4*)(smem + OFF_OBS);
#pragma unroll
        for (int i = tid; i < NTOK * DOBS / 4; i += 256) s4[i] = g4[i];
    }
    __syncthreads();

    // ---- enc1: h = relu(obs @ W1 + b1), 64x128 ----
    gemm_s<128, 128, 128, 128, 4, 8, true>(tid, smem + OFF_OBS, enc_w1, enc_b1, smem + OFF_H);
    __syncthreads();

    // ---- enc2: msgs = h @ W2 + b2, 64x64 ----
    gemm_s<128, 128, 64, 64, 4, 4, false>(tid, smem + OFF_H, enc_w2, enc_b2, smem + OFF_MSG);
    __syncthreads();

    // ---- write msgs to gmem (second output) ----
    if (outM) {
        float4* gm = (float4*)(outM + (size_t)b * NTOK * DMSG);
        const float4* sm4 = (const float4*)(smem + OFF_MSG);
#pragma unroll
        for (int i = tid; i < NTOK * DMSG / 4; i += 256) gm[i] = sm4[i];
    }

    // ---- qkv: msgs @ in_proj (64x192), padded rows ----
    gemm_s<64, 64, 192, LD_QKV, 3, 16, false>(tid, smem + OFF_MSG, inp_w, inp_b, smem + OFF_QKV);
    __syncthreads();

    // ---- attention: thread = (head, query row); 2-pass recompute softmax ----
    {
        const int h = tid >> 6;      // 0..3
        const int q = tid & 63;      // 0..63
        const float* sQ = smem + OFF_QKV;
        float qv[HDIM];
#pragma unroll
        for (int d = 0; d < HDIM; d++) qv[d] = sQ[q * LD_QKV + h * HDIM + d];

        // pass 1: row max
        float m = -1e30f;
#pragma unroll 4
        for (int k = 0; k < NTOK; k++) {
            const float* kp = sQ + k * LD_QKV + DMSG + h * HDIM;
            float s = 0.f;
#pragma unroll
            for (int d = 0; d < HDIM; d++) s = fmaf(qv[d], kp[d], s);
            m = fmaxf(m, s * 0.25f);
        }
        // pass 2: recompute score, accumulate exp-weighted V and sum
        float ssum = 0.f;
        float ctx[HDIM];
#pragma unroll
        for (int d = 0; d < HDIM; d++) ctx[d] = 0.f;
#pragma unroll 2
        for (int k = 0; k < NTOK; k++) {
            const float* kp = sQ + k * LD_QKV + DMSG + h * HDIM;
            float s = 0.f;
#pragma unroll
            for (int d = 0; d < HDIM; d++) s = fmaf(qv[d], kp[d], s);
            float p = __expf(fmaf(s, 0.25f, -m));
            ssum += p;
            const float* vp = sQ + k * LD_QKV + 2 * DMSG + h * HDIM;
#pragma unroll
            for (int d = 0; d < HDIM; d++) ctx[d] = fmaf(p, vp[d], ctx[d]);
        }
        float inv = 1.f / ssum;
        float* so = smem + OFF_CTX;
#pragma unroll
        for (int d = 0; d < HDIM; d++) so[q * LD_CTX + h * HDIM + d] = ctx[d] * inv;
    }
    __syncthreads();

    // ---- out projection: agg = ctx @ out_w + out_b ----
    gemm_s<64, LD_CTX, 64, 64, 4, 4, false>(tid, smem + OFF_CTX, out_w, out_b, smem + OFF_AGG);
    __syncthreads();

    // ---- int1 (concat GEMM): z = [obs | agg] @ int_w1 + int_b1, 64x256 ----
    {
        constexpr int TJ = 4, TT = 16, JG = 64;
        const int jg = tid % JG, tg = tid / JG;
        const int j0 = jg * TJ, t0 = tg * TT;
        float acc[TT][TJ];
#pragma unroll
        for (int jj = 0; jj < TJ; jj++) {
            float bv = int_b1[j0 + jj];
#pragma unroll
            for (int t = 0; t < TT; t++) acc[t][jj] = bv;
        }
        const float* sX1 = smem + OFF_OBS;
#pragma unroll 2
        for (int k = 0; k < DOBS; k++) {
            float w[TJ];
#pragma unroll
            for (int jj = 0; jj < TJ; jj++) w[jj] = int_w1[k * DINT + j0 + jj];
            float x[TT];
#pragma unroll
            for (int t = 0; t < TT; t++) x[t] = sX1[(t0 + t) * DOBS + k];
#pragma unroll
            for (int t = 0; t < TT; t++)
#pragma unroll
                for (int jj = 0; jj < TJ; jj++)
                    acc[t][jj] = fmaf(x[t], w[jj], acc[t][jj]);
        }
        const float* sX2 = smem + OFF_AGG;
#pragma unroll 2
        for (int k = 0; k < DMSG; k++) {
            float w[TJ];
#pragma unroll
            for (int jj = 0; jj < TJ; jj++) w[jj] = int_w1[(DOBS + k) * DINT + j0 + jj];
            float x[TT];
#pragma unroll
            for (int t = 0; t < TT; t++) x[t] = sX2[(t0 + t) * DMSG + k];
#pragma unroll
            for (int t = 0; t < TT; t++)
#pragma unroll
                for (int jj = 0; jj < TJ; jj++)
                    acc[t][jj] = fmaf(x[t], w[jj], acc[t][jj]);
        }
        float* sZ = smem + OFF_Z;
#pragma unroll
        for (int t = 0; t < TT; t++)
#pragma unroll
            for (int jj = 0; jj < TJ; jj++)
                sZ[(t0 + t) * LD_Z + j0 + jj] = acc[t][jj];
    }
    __syncthreads();

    // ---- LayerNorm(256) + ReLU, in place on sZ. 4 threads per token. ----
    {
        const int t = tid >> 2, s = tid & 3;
        float* zr = smem + OFF_Z + t * LD_Z;
        float sum = 0.f, sq = 0.f;
#pragma unroll
        for (int i = 0; i < 64; i++) {
            float v = zr[s + 4 * i];
            sum += v;
            sq = fmaf(v, v, sq);
        }
        sum += __shfl_xor_sync(0xffffffffu, sum, 1);
        sum += __shfl_xor_sync(0xffffffffu, sum, 2);
        sq  += __shfl_xor_sync(0xffffffffu, sq, 1);
        sq  += __shfl_xor_sync(0xffffffffu, sq, 2);
        float mu   = sum * (1.f / 256.f);
        float var  = sq * (1.f / 256.f) - mu * mu;
        float rstd = rsqrtf(var + 1e-5f);
#pragma unroll
        for (int i = 0; i < 64; i++) {
            int c = s + 4 * i;
            float v = zr[c];
            v = (v - mu) * rstd * ln_g[c] + ln_b[c];
            zr[c] = fmaxf(v, 0.f);
        }
    }
    __syncthreads();

    // ---- int2: enriched = relu(z) @ int_w2 + int_b2 -> gmem ----
    {
        constexpr int TJ = 4, TT = 8, JG = 32;
        const int jg = tid % JG, tg = tid / JG;
        const int j0 = jg * TJ, t0 = tg * TT;
        float acc[TT][TJ];
#pragma unroll
        for (int jj = 0; jj < TJ; jj++) {
            float bv = int_b2[j0 + jj];
#pragma unroll
            for (int t = 0; t < TT; t++) acc[t][jj] = bv;
        }
        const float* sZ = smem + OFF_Z;
#pragma unroll 2
        for (int k = 0; k < DINT; k++) {
            float w[TJ];
#pragma unroll
            for (int jj = 0; jj < TJ; jj++) w[jj] = int_w2[k * DOBS + j0 + jj];
            float x[TT];
#pragma unroll
            for (int t = 0; t < TT; t++) x[t] = sZ[(t0 + t) * LD_Z + k];
#pragma unroll
            for (int t = 0; t < TT; t++)
#pragma unroll
                for (int jj = 0; jj < TJ; jj++)
                    acc[t][jj] = fmaf(x[t], w[jj], acc[t][jj]);
        }
        float* go = outE + (size_t)b * NTOK * DOBS;
#pragma unroll
        for (int t = 0; t < TT; t++) {
            float4 v = make_float4(acc[t][0], acc[t][1], acc[t][2], acc[t][3]);
            *(float4*)(go + (t0 + t) * DOBS + j0) = v;
        }
    }
}

extern "C" void kernel_launch(void* const* d_in, const int* in_sizes, int n_in,
                              void* d_out, int out_size)
{
    const float* obs    = (const float*)d_in[0];
    const float* enc_w1 = (const float*)d_in[1];
    const float* enc_b1 = (const float*)d_in[2];
    const float* enc_w2 = (const float*)d_in[3];
    const float* enc_b2 = (const float*)d_in[4];
    const float* inp_w  = (const float*)d_in[5];
    const float* inp_b  = (const float*)d_in[6];
    const float* out_w  = (const float*)d_in[7];
    const float* out_b  = (const float*)d_in[8];
    const float* int_w1 = (const float*)d_in[9];
    const float* int_b1 = (const float*)d_in[10];
    const float* ln_g   = (const float*)d_in[11];
    const float* ln_b   = (const float*)d_in[12];
    const float* int_w2 = (const float*)d_in[13];
    const float* int_b2 = (const float*)d_in[14];

    float* outE = (float*)d_out;
    const size_t esz = (size_t)NBATCH * NTOK * DOBS;
    // Reference returns (enriched, msgs): msgs follow enriched if out buffer holds both.
    float* outM = ((size_t)out_size > esz) ? outE + esz : nullptr;

    cudaFuncSetAttribute(macs_kernel, cudaFuncAttributeMaxDynamicSharedMemorySize, SMEM_BYTES);
    macs_kernel<<<NBATCH, 256, SMEM_BYTES>>>(
        obs, enc_w1, enc_b1, enc_w2, enc_b2,
        inp_w, inp_b, out_w, out_b,
        int_w1, int_b1, ln_g, ln_b, int_w2, int_b2,
        outE, outM);
}